// round 11
// baseline (speedup 1.0000x reference)
#include <cuda_runtime.h>
#include <cuda_fp16.h>
#include <cstdint>

// Problem constants (fixed shapes: N=2048, F=512, E=32)
#define FDIM 512
#define EDIM 32
#define NWARPS 8
#define NTHREADS (NWARPS * 32)
#define ROWH 40   // halves per FX row (80 B). 8-row ldmatrix groups span all 32 banks.
#define ROWB (ROWH * 2)

__device__ __forceinline__ float warpSum(float v) {
#pragma unroll
    for (int o = 16; o; o >>= 1) v += __shfl_xor_sync(0xffffffffu, v, o);
    return v;
}

__device__ __forceinline__ void ldmx4(uint32_t& r0, uint32_t& r1, uint32_t& r2, uint32_t& r3,
                                      uint32_t addr) {
    asm volatile("ldmatrix.sync.aligned.m8n8.x4.shared.b16 {%0,%1,%2,%3}, [%4];"
                 : "=r"(r0), "=r"(r1), "=r"(r2), "=r"(r3) : "r"(addr));
}
__device__ __forceinline__ void ldmx4t(uint32_t& r0, uint32_t& r1, uint32_t& r2, uint32_t& r3,
                                       uint32_t addr) {
    asm volatile("ldmatrix.sync.aligned.m8n8.x4.trans.shared.b16 {%0,%1,%2,%3}, [%4];"
                 : "=r"(r0), "=r"(r1), "=r"(r2), "=r"(r3) : "r"(addr));
}
__device__ __forceinline__ void mma16816(float& d0, float& d1, float& d2, float& d3,
                                         uint32_t a0, uint32_t a1, uint32_t a2, uint32_t a3,
                                         uint32_t b0, uint32_t b1) {
    asm volatile("mma.sync.aligned.m16n8k16.row.col.f32.f16.f16.f32 "
                 "{%0,%1,%2,%3},{%4,%5,%6,%7},{%8,%9},{%0,%1,%2,%3};"
                 : "+f"(d0), "+f"(d1), "+f"(d2), "+f"(d3)
                 : "r"(a0), "r"(a1), "r"(a2), "r"(a3), "r"(b0), "r"(b1));
}

// Shared layout:
//   FXh   : FDIM*ROWH halves = 40960 B   compacted FX (fp16), 40-half row stride
//   bsel  : EDIM floats                  xs_b[idx_n, :]
//   fxs   : EDIM floats                  sum_q o[q]/u[q] accumulator
//   vlist : FDIM ints                    compacted valid-key indices
//   sints : 2 ints                       [0]=cnt, [1]=idx
#define SMEM_BYTES (FDIM*ROWH*2 + EDIM*4 + EDIM*4 + FDIM*4 + 8)

__global__ __launch_bounds__(NTHREADS, 2)
void model_simple_kernel(const float* __restrict__ X,
                         const float* __restrict__ Xi,
                         const float* __restrict__ Ioh,
                         const float* __restrict__ S,
                         const float* __restrict__ xi_w,
                         const float* __restrict__ xi_b,
                         const float* __restrict__ xs_w,
                         const float* __restrict__ xs_b,
                         float* __restrict__ out)
{
    extern __shared__ float smem[];
    __half* FXh  = (__half*)smem;                    // FDIM*ROWH halves
    float* bsel  = smem + FDIM * ROWH / 2;           // EDIM
    float* fxs   = bsel + EDIM;                      // EDIM
    int*   vlist = (int*)(fxs + EDIM);               // FDIM
    int*   sints = vlist + FDIM;                     // 2

    const int n    = blockIdx.x;
    const int tid  = threadIdx.x;
    const int lane = tid & 31;
    const int wid  = tid >> 5;

    // ---- init + find one-hot index ----
    if (tid < EDIM) fxs[tid] = 0.f;
    for (int f = tid; f < FDIM; f += NTHREADS)
        if (Ioh[(size_t)n * FDIM + f] != 0.f) sints[1] = f;   // exactly one nonzero
    __syncthreads();

    // ---- deterministic compaction of valid keys (warp 0); bsel gather (warp 1) ----
    if (wid == 0) {
        int c = 0;
        for (int base = 0; base < FDIM; base += 32) {
            float sv = S[(size_t)n * FDIM + base + lane];
            unsigned b = __ballot_sync(0xffffffffu, sv != 0.f);
            if (sv != 0.f) vlist[c + __popc(b & ((1u << lane) - 1u))] = base + lane;
            c += __popc(b);
        }
        if (lane == 0) sints[0] = c;
    } else if (wid == 1) {
        bsel[lane] = xs_b[sints[1] * EDIM + lane];
    }
    __syncthreads();

    const int cnt  = sints[0];             // >= 1 (S[:,0]=1 guaranteed)
    const int nqt  = ((cnt + 31) >> 5) << 1;   // 16-row tiles, rounded up to EVEN
    const int nqtp = nqt >> 1;                 // qtile pairs per warp-sweep
    const int nrows = nqt << 4;

    // ---- build compacted FX (fp16): FXh[i][e] = X[n,k_i]*xs_w[k_i,e]+xs_b[k_i,e]+bsel[e] ----
    for (int i = tid; i < cnt; i += NTHREADS) {
        int k = vlist[i];
        float x = X[(size_t)n * FDIM + k];
        const float4* w4 = (const float4*)(xs_w + k * EDIM);
        const float4* b4 = (const float4*)(xs_b + k * EDIM);
        float4* dst = (float4*)(FXh + (size_t)i * ROWH);   // 80 B stride, 16B-aligned
#pragma unroll
        for (int m = 0; m < 4; m++) {
            float4 w0 = w4[2*m],     b0 = b4[2*m];
            float4 w1 = w4[2*m + 1], b1 = b4[2*m + 1];
            float o0 = fmaf(x, w0.x, b0.x) + bsel[m*8 + 0];
            float o1 = fmaf(x, w0.y, b0.y) + bsel[m*8 + 1];
            float o2 = fmaf(x, w0.z, b0.z) + bsel[m*8 + 2];
            float o3 = fmaf(x, w0.w, b0.w) + bsel[m*8 + 3];
            float o4 = fmaf(x, w1.x, b1.x) + bsel[m*8 + 4];
            float o5 = fmaf(x, w1.y, b1.y) + bsel[m*8 + 5];
            float o6 = fmaf(x, w1.z, b1.z) + bsel[m*8 + 6];
            float o7 = fmaf(x, w1.w, b1.w) + bsel[m*8 + 7];
            float4 pk;
            ((__half2*)&pk)[0] = __floats2half2_rn(o0, o1);
            ((__half2*)&pk)[1] = __floats2half2_rn(o2, o3);
            ((__half2*)&pk)[2] = __floats2half2_rn(o4, o5);
            ((__half2*)&pk)[3] = __floats2half2_rn(o6, o7);
            dst[m] = pk;
        }
    }
    // zero-pad tail rows (padded keys masked to e=0; padded queries die via inv=0)
    for (int i = cnt + tid; i < nrows; i += NTHREADS) {
        float4* dst = (float4*)(FXh + (size_t)i * ROWH);
#pragma unroll
        for (int m = 0; m < 4; m++) dst[m] = make_float4(0.f, 0.f, 0.f, 0.f);
    }
    __syncthreads();

    const float SCALE = 0.17677669529663687f;  // 1/sqrt(32)
    const uint32_t smemFX = (uint32_t)__cvta_generic_to_shared(FXh);

    // ldmatrix address components (bytes); FX row stride = 80 B.
    const uint32_t aoff = (uint32_t)(lane & 15) * ROWB + (uint32_t)(lane >> 4) * 16;
    const uint32_t boff = (uint32_t)(lane & 7) * ROWB
                        + (uint32_t)((lane >> 3) & 1) * 16
                        + (uint32_t)(lane >> 4) * (8 * ROWB);
    const uint32_t voff = aoff;   // trans load

    const int gr = lane >> 2;          // row group 0..7
    const int tc = lane & 3;           // col thread 0..3

    // ---- attention: single pass, 2 warp-private 16-query tiles share B/V frags ----
    for (int p = wid; p < nqtp; p += NWARPS) {
        const int q0a = p << 4;
        const int q0b = (p + nqtp) << 4;   // < nrows by construction
        uint32_t a0l[4], a0h[4], a1l[4], a1h[4];
        {
            uint32_t ad = smemFX + (uint32_t)q0a * ROWB + aoff;
            ldmx4(a0l[0], a0l[1], a0l[2], a0l[3], ad);
            ldmx4(a0h[0], a0h[1], a0h[2], a0h[3], ad + 32);
            ad = smemFX + (uint32_t)q0b * ROWB + aoff;
            ldmx4(a1l[0], a1l[1], a1l[2], a1l[3], ad);
            ldmx4(a1h[0], a1h[1], a1h[2], a1h[3], ad + 32);
        }
        float oa[16], ob[16];
#pragma unroll
        for (int i = 0; i < 16; i++) { oa[i] = 0.f; ob[i] = 0.f; }
        float u0 = 0.f, u1 = 0.f, u2 = 0.f, u3 = 0.f;

        uint32_t bd = smemFX + boff;
        uint32_t vd = smemFX + voff;
        for (int kt = 0; kt < nqt; kt++, bd += 16 * ROWB, vd += 16 * ROWB) {
            const int k0 = kt << 4;
            // ---- QK for both qtiles: shared B frags ----
            uint32_t bl[4], bh[4];
            ldmx4(bl[0], bl[1], bl[2], bl[3], bd);        // e 0-15
            ldmx4(bh[0], bh[1], bh[2], bh[3], bd + 32);   // e 16-31
            float c0 = 0.f, c1 = 0.f, c2 = 0.f, c3 = 0.f;   // qt0, keys lo
            float d0 = 0.f, d1 = 0.f, d2 = 0.f, d3 = 0.f;   // qt0, keys hi
            float g0 = 0.f, g1 = 0.f, g2 = 0.f, g3 = 0.f;   // qt1, keys lo
            float h0 = 0.f, h1 = 0.f, h2 = 0.f, h3 = 0.f;   // qt1, keys hi
            mma16816(c0, c1, c2, c3, a0l[0], a0l[1], a0l[2], a0l[3], bl[0], bl[1]);
            mma16816(c0, c1, c2, c3, a0h[0], a0h[1], a0h[2], a0h[3], bh[0], bh[1]);
            mma16816(d0, d1, d2, d3, a0l[0], a0l[1], a0l[2], a0l[3], bl[2], bl[3]);
            mma16816(d0, d1, d2, d3, a0h[0], a0h[1], a0h[2], a0h[3], bh[2], bh[3]);
            mma16816(g0, g1, g2, g3, a1l[0], a1l[1], a1l[2], a1l[3], bl[0], bl[1]);
            mma16816(g0, g1, g2, g3, a1h[0], a1h[1], a1h[2], a1h[3], bh[0], bh[1]);
            mma16816(h0, h1, h2, h3, a1l[0], a1l[1], a1l[2], a1l[3], bl[2], bl[3]);
            mma16816(h0, h1, h2, h3, a1h[0], a1h[1], a1h[2], a1h[3], bh[2], bh[3]);

            // ---- exp; masks only in the (rare) boundary tiles ----
            float ec0, ec1, ec2, ec3, ed0, ed1, ed2, ed3;
            float eg0, eg1, eg2, eg3, eh0, eh1, eh2, eh3;
            if (k0 + 16 <= cnt) {   // full tile: no masks (uniform branch)
                ec0 = __expf(c0 * SCALE); ec1 = __expf(c1 * SCALE);
                ec2 = __expf(c2 * SCALE); ec3 = __expf(c3 * SCALE);
                ed0 = __expf(d0 * SCALE); ed1 = __expf(d1 * SCALE);
                ed2 = __expf(d2 * SCALE); ed3 = __expf(d3 * SCALE);
                eg0 = __expf(g0 * SCALE); eg1 = __expf(g1 * SCALE);
                eg2 = __expf(g2 * SCALE); eg3 = __expf(g3 * SCALE);
                eh0 = __expf(h0 * SCALE); eh1 = __expf(h1 * SCALE);
                eh2 = __expf(h2 * SCALE); eh3 = __expf(h3 * SCALE);
            } else {
                const int ka = k0 + 2 * tc, kb = ka + 8;
                bool va = ka < cnt, va1 = ka + 1 < cnt;
                bool vb = kb < cnt, vb1 = kb + 1 < cnt;
                ec0 = va  ? __expf(c0 * SCALE) : 0.f;
                ec1 = va1 ? __expf(c1 * SCALE) : 0.f;
                ec2 = va  ? __expf(c2 * SCALE) : 0.f;
                ec3 = va1 ? __expf(c3 * SCALE) : 0.f;
                ed0 = vb  ? __expf(d0 * SCALE) : 0.f;
                ed1 = vb1 ? __expf(d1 * SCALE) : 0.f;
                ed2 = vb  ? __expf(d2 * SCALE) : 0.f;
                ed3 = vb1 ? __expf(d3 * SCALE) : 0.f;
                eg0 = va  ? __expf(g0 * SCALE) : 0.f;
                eg1 = va1 ? __expf(g1 * SCALE) : 0.f;
                eg2 = va  ? __expf(g2 * SCALE) : 0.f;
                eg3 = va1 ? __expf(g3 * SCALE) : 0.f;
                eh0 = vb  ? __expf(h0 * SCALE) : 0.f;
                eh1 = vb1 ? __expf(h1 * SCALE) : 0.f;
                eh2 = vb  ? __expf(h2 * SCALE) : 0.f;
                eh3 = vb1 ? __expf(h3 * SCALE) : 0.f;
            }
            u0 += (ec0 + ec1) + (ed0 + ed1);
            u1 += (ec2 + ec3) + (ed2 + ed3);
            u2 += (eg0 + eg1) + (eh0 + eh1);
            u3 += (eg2 + eg3) + (eh2 + eh3);

            // ---- pack P to fp16 A-frags (C-frag -> A-frag identity) ----
            __half2 p0 = __floats2half2_rn(ec0, ec1);
            __half2 p1 = __floats2half2_rn(ec2, ec3);
            __half2 p2 = __floats2half2_rn(ed0, ed1);
            __half2 p3 = __floats2half2_rn(ed2, ed3);
            __half2 r0 = __floats2half2_rn(eg0, eg1);
            __half2 r1 = __floats2half2_rn(eg2, eg3);
            __half2 r2 = __floats2half2_rn(eh0, eh1);
            __half2 r3 = __floats2half2_rn(eh2, eh3);
            uint32_t A0 = *(uint32_t*)&p0, A1 = *(uint32_t*)&p1;
            uint32_t A2 = *(uint32_t*)&p2, A3 = *(uint32_t*)&p3;
            uint32_t B0 = *(uint32_t*)&r0, B1 = *(uint32_t*)&r1;
            uint32_t B2 = *(uint32_t*)&r2, B3 = *(uint32_t*)&r3;

            // ---- PV for both qtiles: shared V frags ----
            uint32_t vl[4], vh[4];
            ldmx4t(vl[0], vl[1], vl[2], vl[3], vd);        // e 0-15
            ldmx4t(vh[0], vh[1], vh[2], vh[3], vd + 32);   // e 16-31
            mma16816(oa[0],  oa[1],  oa[2],  oa[3],  A0, A1, A2, A3, vl[0], vl[1]);
            mma16816(oa[4],  oa[5],  oa[6],  oa[7],  A0, A1, A2, A3, vl[2], vl[3]);
            mma16816(oa[8],  oa[9],  oa[10], oa[11], A0, A1, A2, A3, vh[0], vh[1]);
            mma16816(oa[12], oa[13], oa[14], oa[15], A0, A1, A2, A3, vh[2], vh[3]);
            mma16816(ob[0],  ob[1],  ob[2],  ob[3],  B0, B1, B2, B3, vl[0], vl[1]);
            mma16816(ob[4],  ob[5],  ob[6],  ob[7],  B0, B1, B2, B3, vl[2], vl[3]);
            mma16816(ob[8],  ob[9],  ob[10], ob[11], B0, B1, B2, B3, vh[0], vh[1]);
            mma16816(ob[12], ob[13], ob[14], ob[15], B0, B1, B2, B3, vh[2], vh[3]);
        }

        // row sums: reduce over the 4 col-threads
        u0 += __shfl_xor_sync(0xffffffffu, u0, 1);
        u0 += __shfl_xor_sync(0xffffffffu, u0, 2);
        u1 += __shfl_xor_sync(0xffffffffu, u1, 1);
        u1 += __shfl_xor_sync(0xffffffffu, u1, 2);
        u2 += __shfl_xor_sync(0xffffffffu, u2, 1);
        u2 += __shfl_xor_sync(0xffffffffu, u2, 2);
        u3 += __shfl_xor_sync(0xffffffffu, u3, 1);
        u3 += __shfl_xor_sync(0xffffffffu, u3, 2);
        const float inv0 = (q0a + gr     < cnt) ? 1.f / u0 : 0.f;
        const float inv1 = (q0a + gr + 8 < cnt) ? 1.f / u1 : 0.f;
        const float inv2 = (q0b + gr     < cnt) ? 1.f / u2 : 0.f;
        const float inv3 = (q0b + gr + 8 < cnt) ? 1.f / u3 : 0.f;

        // normalize, reduce over rows, accumulate into fxs
#pragma unroll
        for (int j = 0; j < 4; j++) {
            float s0 = oa[4*j + 0] * inv0 + oa[4*j + 2] * inv1
                     + ob[4*j + 0] * inv2 + ob[4*j + 2] * inv3;   // col 8j + 2tc
            float s1 = oa[4*j + 1] * inv0 + oa[4*j + 3] * inv1
                     + ob[4*j + 1] * inv2 + ob[4*j + 3] * inv3;   // col 8j + 2tc + 1
            s0 += __shfl_xor_sync(0xffffffffu, s0, 4);
            s0 += __shfl_xor_sync(0xffffffffu, s0, 8);
            s0 += __shfl_xor_sync(0xffffffffu, s0, 16);
            s1 += __shfl_xor_sync(0xffffffffu, s1, 4);
            s1 += __shfl_xor_sync(0xffffffffu, s1, 8);
            s1 += __shfl_xor_sync(0xffffffffu, s1, 16);
            if (lane < 4) {
                atomicAdd(&fxs[8*j + 2*lane],     s0);
                atomicAdd(&fxs[8*j + 2*lane + 1], s1);
            }
        }
    }
    __syncthreads();

    // ---- epilogue (warp 0) ----
    if (wid == 0) {
        int idx = sints[1];
        float f  = fxs[lane] / (float)cnt;
        float iw = xi_w[idx * EDIM + lane];
        float ib = xi_b[idx * EDIM + lane];
        float t0 = warpSum(ib * f);           // Xi = 0 branch
        float t1 = warpSum((iw + ib) * f);    // Xi = 1 branch
        if (lane == 0) {
            float xi = Xi[n];
            float ul = t0 + xi * (t1 - t0);   // sum(Fxi * Fxs)
            float M  = fmaxf(t0, t1);
            float lz = M + logf(__expf(t0 - M) + __expf(t1 - M));
            out[n] = ul - lz;
        }
    }
}

extern "C" void kernel_launch(void* const* d_in, const int* in_sizes, int n_in,
                              void* d_out, int out_size)
{
    const float* X    = (const float*)d_in[0];
    const float* Xi   = (const float*)d_in[1];
    const float* Ioh  = (const float*)d_in[2];
    const float* S    = (const float*)d_in[3];
    const float* xi_w = (const float*)d_in[4];
    const float* xi_b = (const float*)d_in[5];
    const float* xs_w = (const float*)d_in[6];
    const float* xs_b = (const float*)d_in[7];
    float* out = (float*)d_out;

    const int N = in_sizes[1];  // Xi length = batch

    // Unconditional (no static guard): non-stream host API, capture-safe, idempotent.
    cudaFuncSetAttribute(model_simple_kernel,
                         cudaFuncAttributeMaxDynamicSharedMemorySize, SMEM_BYTES);

    model_simple_kernel<<<N, NTHREADS, SMEM_BYTES>>>(
        X, Xi, Ioh, S, xi_w, xi_b, xs_w, xs_b, out);
}

// round 12
// speedup vs baseline: 1.2718x; 1.2718x over previous
#include <cuda_runtime.h>
#include <cuda_fp16.h>
#include <cstdint>

// Problem constants (fixed shapes: N=2048, F=512, E=32)
#define FDIM 512
#define EDIM 32
#define NWARPS 8
#define NTHREADS (NWARPS * 32)
#define ROWH 40   // halves per FX row (80 B). 8-row ldmatrix groups span all 32 banks.
#define ROWB (ROWH * 2)

__device__ __forceinline__ float warpSum(float v) {
#pragma unroll
    for (int o = 16; o; o >>= 1) v += __shfl_xor_sync(0xffffffffu, v, o);
    return v;
}
__device__ __forceinline__ float ex2(float x) {   // 2^x
    float r;
    asm("ex2.approx.ftz.f32 %0, %1;" : "=f"(r) : "f"(x));
    return r;
}

__device__ __forceinline__ void ldmx4(uint32_t& r0, uint32_t& r1, uint32_t& r2, uint32_t& r3,
                                      uint32_t addr) {
    asm volatile("ldmatrix.sync.aligned.m8n8.x4.shared.b16 {%0,%1,%2,%3}, [%4];"
                 : "=r"(r0), "=r"(r1), "=r"(r2), "=r"(r3) : "r"(addr));
}
__device__ __forceinline__ void ldmx4t(uint32_t& r0, uint32_t& r1, uint32_t& r2, uint32_t& r3,
                                       uint32_t addr) {
    asm volatile("ldmatrix.sync.aligned.m8n8.x4.trans.shared.b16 {%0,%1,%2,%3}, [%4];"
                 : "=r"(r0), "=r"(r1), "=r"(r2), "=r"(r3) : "r"(addr));
}
__device__ __forceinline__ void mma16816(float& d0, float& d1, float& d2, float& d3,
                                         uint32_t a0, uint32_t a1, uint32_t a2, uint32_t a3,
                                         uint32_t b0, uint32_t b1) {
    asm volatile("mma.sync.aligned.m16n8k16.row.col.f32.f16.f16.f32 "
                 "{%0,%1,%2,%3},{%4,%5,%6,%7},{%8,%9},{%0,%1,%2,%3};"
                 : "+f"(d0), "+f"(d1), "+f"(d2), "+f"(d3)
                 : "r"(a0), "r"(a1), "r"(a2), "r"(a3), "r"(b0), "r"(b1));
}

// Shared layout:
//   FXh   : FDIM*ROWH halves = 40960 B   compacted FX (fp16), 40-half row stride
//   bsel  : EDIM floats                  xs_b[idx_n, :]
//   fxs   : EDIM floats                  sum_q o[q]/u[q] accumulator
//   vlist : FDIM ints                    compacted valid-key indices
//   sints : 2 ints                       [0]=cnt, [1]=idx
#define SMEM_BYTES (FDIM*ROWH*2 + EDIM*4 + EDIM*4 + FDIM*4 + 8)

__global__ __launch_bounds__(NTHREADS, 3)
void model_simple_kernel(const float* __restrict__ X,
                         const float* __restrict__ Xi,
                         const float* __restrict__ Ioh,
                         const float* __restrict__ S,
                         const float* __restrict__ xi_w,
                         const float* __restrict__ xi_b,
                         const float* __restrict__ xs_w,
                         const float* __restrict__ xs_b,
                         float* __restrict__ out)
{
    extern __shared__ float smem[];
    __half* FXh  = (__half*)smem;                    // FDIM*ROWH halves
    float* bsel  = smem + FDIM * ROWH / 2;           // EDIM
    float* fxs   = bsel + EDIM;                      // EDIM
    int*   vlist = (int*)(fxs + EDIM);               // FDIM
    int*   sints = vlist + FDIM;                     // 2

    const int n    = blockIdx.x;
    const int tid  = threadIdx.x;
    const int lane = tid & 31;
    const int wid  = tid >> 5;

    // ---- init + find one-hot index ----
    if (tid < EDIM) fxs[tid] = 0.f;
    for (int f = tid; f < FDIM; f += NTHREADS)
        if (Ioh[(size_t)n * FDIM + f] != 0.f) sints[1] = f;   // exactly one nonzero
    __syncthreads();

    // ---- deterministic compaction of valid keys (warp 0); bsel gather (warp 1) ----
    if (wid == 0) {
        int c = 0;
        for (int base = 0; base < FDIM; base += 32) {
            float sv = S[(size_t)n * FDIM + base + lane];
            unsigned b = __ballot_sync(0xffffffffu, sv != 0.f);
            if (sv != 0.f) vlist[c + __popc(b & ((1u << lane) - 1u))] = base + lane;
            c += __popc(b);
        }
        if (lane == 0) sints[0] = c;
    } else if (wid == 1) {
        bsel[lane] = xs_b[sints[1] * EDIM + lane];
    }
    __syncthreads();

    const int cnt = sints[0];              // >= 1 (S[:,0]=1 guaranteed)
    const int nqt = (cnt + 15) >> 4;       // 16-row tiles (queries AND keys)
    const int nrows = nqt << 4;

    // ---- build compacted FX (fp16): FXh[i][e] = X[n,k_i]*xs_w[k_i,e]+xs_b[k_i,e]+bsel[e] ----
    for (int i = tid; i < cnt; i += NTHREADS) {
        int k = vlist[i];
        float x = X[(size_t)n * FDIM + k];
        const float4* w4 = (const float4*)(xs_w + k * EDIM);
        const float4* b4 = (const float4*)(xs_b + k * EDIM);
        float4* dst = (float4*)(FXh + (size_t)i * ROWH);   // 80 B stride, 16B-aligned
#pragma unroll
        for (int m = 0; m < 4; m++) {
            float4 w0 = w4[2*m],     b0 = b4[2*m];
            float4 w1 = w4[2*m + 1], b1 = b4[2*m + 1];
            float o0 = fmaf(x, w0.x, b0.x) + bsel[m*8 + 0];
            float o1 = fmaf(x, w0.y, b0.y) + bsel[m*8 + 1];
            float o2 = fmaf(x, w0.z, b0.z) + bsel[m*8 + 2];
            float o3 = fmaf(x, w0.w, b0.w) + bsel[m*8 + 3];
            float o4 = fmaf(x, w1.x, b1.x) + bsel[m*8 + 4];
            float o5 = fmaf(x, w1.y, b1.y) + bsel[m*8 + 5];
            float o6 = fmaf(x, w1.z, b1.z) + bsel[m*8 + 6];
            float o7 = fmaf(x, w1.w, b1.w) + bsel[m*8 + 7];
            float4 pk;
            ((__half2*)&pk)[0] = __floats2half2_rn(o0, o1);
            ((__half2*)&pk)[1] = __floats2half2_rn(o2, o3);
            ((__half2*)&pk)[2] = __floats2half2_rn(o4, o5);
            ((__half2*)&pk)[3] = __floats2half2_rn(o6, o7);
            dst[m] = pk;
        }
    }
    // zero-pad tail rows (padded keys masked to e=0; padded queries die via inv=0)
    for (int i = cnt + tid; i < nrows; i += NTHREADS) {
        float4* dst = (float4*)(FXh + (size_t)i * ROWH);
#pragma unroll
        for (int m = 0; m < 4; m++) dst[m] = make_float4(0.f, 0.f, 0.f, 0.f);
    }
    __syncthreads();

    const float SC2 = 0.25508329533403174f;  // (1/sqrt(32)) * log2(e)
    const uint32_t smemFX = (uint32_t)__cvta_generic_to_shared(FXh);

    // ldmatrix address components (bytes); FX row stride = 80 B.
    const uint32_t aoff = (uint32_t)(lane & 15) * ROWB + (uint32_t)(lane >> 4) * 16;
    const uint32_t boff = (uint32_t)(lane & 7) * ROWB
                        + (uint32_t)((lane >> 3) & 1) * 16
                        + (uint32_t)(lane >> 4) * (8 * ROWB);
    const uint32_t voff = aoff;   // trans load

    const int gr = lane >> 2;          // row group 0..7
    const int tc = lane & 3;           // col thread 0..3

    // ---- attention: single pass, warp-private 16-query tiles ----
    for (int qt = wid; qt < nqt; qt += NWARPS) {
        const int q0 = qt << 4;
        uint32_t alo[4], ahi[4];
        {
            uint32_t ad = smemFX + (uint32_t)q0 * ROWB + aoff;
            ldmx4(alo[0], alo[1], alo[2], alo[3], ad);        // e 0-15
            ldmx4(ahi[0], ahi[1], ahi[2], ahi[3], ad + 32);   // e 16-31
        }
        float oa[16];
#pragma unroll
        for (int i = 0; i < 16; i++) oa[i] = 0.f;
        float u0 = 0.f, u1 = 0.f;

        uint32_t bd = smemFX + boff;
        uint32_t vd = smemFX + voff;
        for (int kt = 0; kt < nqt; kt++, bd += 16 * ROWB, vd += 16 * ROWB) {
            const int k0 = kt << 4;
            // ---- load QK B-frags and PV V-frags up front (V latency hides under exp) ----
            uint32_t bl[4], bh[4], vl[4], vh[4];
            ldmx4(bl[0], bl[1], bl[2], bl[3], bd);        // e 0-15
            ldmx4(bh[0], bh[1], bh[2], bh[3], bd + 32);   // e 16-31
            ldmx4t(vl[0], vl[1], vl[2], vl[3], vd);       // e 0-15 (trans)
            ldmx4t(vh[0], vh[1], vh[2], vh[3], vd + 32);  // e 16-31 (trans)

            // ---- QK: P[16 x 16] over 32-e contraction ----
            float c0 = 0.f, c1 = 0.f, c2 = 0.f, c3 = 0.f;   // keys k0+0..7
            float d0 = 0.f, d1 = 0.f, d2 = 0.f, d3 = 0.f;   // keys k0+8..15
            mma16816(c0, c1, c2, c3, alo[0], alo[1], alo[2], alo[3], bl[0], bl[1]);
            mma16816(c0, c1, c2, c3, ahi[0], ahi[1], ahi[2], ahi[3], bh[0], bh[1]);
            mma16816(d0, d1, d2, d3, alo[0], alo[1], alo[2], alo[3], bl[2], bl[3]);
            mma16816(d0, d1, d2, d3, ahi[0], ahi[1], ahi[2], ahi[3], bh[2], bh[3]);

            // ---- exp (scores tiny: no max-shift); masks only in the boundary tile ----
            float ec0, ec1, ec2, ec3, ed0, ed1, ed2, ed3;
            if (k0 + 16 <= cnt) {   // full tile (uniform branch): mask-free
                ec0 = ex2(c0 * SC2); ec1 = ex2(c1 * SC2);
                ec2 = ex2(c2 * SC2); ec3 = ex2(c3 * SC2);
                ed0 = ex2(d0 * SC2); ed1 = ex2(d1 * SC2);
                ed2 = ex2(d2 * SC2); ed3 = ex2(d3 * SC2);
            } else {
                const int ka = k0 + 2 * tc, kb = ka + 8;
                ec0 = (ka     < cnt) ? ex2(c0 * SC2) : 0.f;
                ec1 = (ka + 1 < cnt) ? ex2(c1 * SC2) : 0.f;
                ec2 = (ka     < cnt) ? ex2(c2 * SC2) : 0.f;
                ec3 = (ka + 1 < cnt) ? ex2(c3 * SC2) : 0.f;
                ed0 = (kb     < cnt) ? ex2(d0 * SC2) : 0.f;
                ed1 = (kb + 1 < cnt) ? ex2(d1 * SC2) : 0.f;
                ed2 = (kb     < cnt) ? ex2(d2 * SC2) : 0.f;
                ed3 = (kb + 1 < cnt) ? ex2(d3 * SC2) : 0.f;
            }
            u0 += (ec0 + ec1) + (ed0 + ed1);
            u1 += (ec2 + ec3) + (ed2 + ed3);

            // ---- pack P to fp16 A-frags (C-frag -> A-frag identity) ----
            __half2 h0 = __floats2half2_rn(ec0, ec1);   // (gr,   keys k0+2tc, +1)
            __half2 h1 = __floats2half2_rn(ec2, ec3);   // (gr+8, keys k0+2tc, +1)
            __half2 h2 = __floats2half2_rn(ed0, ed1);   // (gr,   keys k0+8+2tc, +1)
            __half2 h3 = __floats2half2_rn(ed2, ed3);   // (gr+8, keys k0+8+2tc, +1)
            uint32_t A0 = *(uint32_t*)&h0;
            uint32_t A1 = *(uint32_t*)&h1;
            uint32_t A2 = *(uint32_t*)&h2;
            uint32_t A3 = *(uint32_t*)&h3;

            // ---- PV: O[16 x 32] += P * FX[k0:k0+16, :] ----
            mma16816(oa[0],  oa[1],  oa[2],  oa[3],  A0, A1, A2, A3, vl[0], vl[1]); // e0-7
            mma16816(oa[4],  oa[5],  oa[6],  oa[7],  A0, A1, A2, A3, vl[2], vl[3]); // e8-15
            mma16816(oa[8],  oa[9],  oa[10], oa[11], A0, A1, A2, A3, vh[0], vh[1]); // e16-23
            mma16816(oa[12], oa[13], oa[14], oa[15], A0, A1, A2, A3, vh[2], vh[3]); // e24-31
        }

        // row sums: reduce over the 4 col-threads
        u0 += __shfl_xor_sync(0xffffffffu, u0, 1);
        u0 += __shfl_xor_sync(0xffffffffu, u0, 2);
        u1 += __shfl_xor_sync(0xffffffffu, u1, 1);
        u1 += __shfl_xor_sync(0xffffffffu, u1, 2);
        const float inv0 = (q0 + gr     < cnt) ? 1.f / u0 : 0.f;  // u>0 for valid rows
        const float inv1 = (q0 + gr + 8 < cnt) ? 1.f / u1 : 0.f;

        // normalize, reduce over rows, accumulate into fxs
#pragma unroll
        for (int j = 0; j < 4; j++) {
            float s0 = oa[4*j + 0] * inv0 + oa[4*j + 2] * inv1;  // col 8j + 2tc
            float s1 = oa[4*j + 1] * inv0 + oa[4*j + 3] * inv1;  // col 8j + 2tc + 1
            s0 += __shfl_xor_sync(0xffffffffu, s0, 4);
            s0 += __shfl_xor_sync(0xffffffffu, s0, 8);
            s0 += __shfl_xor_sync(0xffffffffu, s0, 16);
            s1 += __shfl_xor_sync(0xffffffffu, s1, 4);
            s1 += __shfl_xor_sync(0xffffffffu, s1, 8);
            s1 += __shfl_xor_sync(0xffffffffu, s1, 16);
            if (lane < 4) {
                atomicAdd(&fxs[8*j + 2*lane],     s0);
                atomicAdd(&fxs[8*j + 2*lane + 1], s1);
            }
        }
    }
    __syncthreads();

    // ---- epilogue (warp 0) ----
    if (wid == 0) {
        int idx = sints[1];
        float f  = fxs[lane] / (float)cnt;
        float iw = xi_w[idx * EDIM + lane];
        float ib = xi_b[idx * EDIM + lane];
        float t0 = warpSum(ib * f);           // Xi = 0 branch
        float t1 = warpSum((iw + ib) * f);    // Xi = 1 branch
        if (lane == 0) {
            float xi = Xi[n];
            float ul = t0 + xi * (t1 - t0);   // sum(Fxi * Fxs)
            float M  = fmaxf(t0, t1);
            float lz = M + logf(__expf(t0 - M) + __expf(t1 - M));
            out[n] = ul - lz;
        }
    }
}

extern "C" void kernel_launch(void* const* d_in, const int* in_sizes, int n_in,
                              void* d_out, int out_size)
{
    const float* X    = (const float*)d_in[0];
    const float* Xi   = (const float*)d_in[1];
    const float* Ioh  = (const float*)d_in[2];
    const float* S    = (const float*)d_in[3];
    const float* xi_w = (const float*)d_in[4];
    const float* xi_b = (const float*)d_in[5];
    const float* xs_w = (const float*)d_in[6];
    const float* xs_b = (const float*)d_in[7];
    float* out = (float*)d_out;

    const int N = in_sizes[1];  // Xi length = batch

    // Unconditional (no static guard): non-stream host API, capture-safe, idempotent.
    cudaFuncSetAttribute(model_simple_kernel,
                         cudaFuncAttributeMaxDynamicSharedMemorySize, SMEM_BYTES);

    model_simple_kernel<<<N, NTHREADS, SMEM_BYTES>>>(
        X, Xi, Ioh, S, xi_w, xi_b, xs_w, xs_b, out);
}